// round 6
// baseline (speedup 1.0000x reference)
#include <cuda_runtime.h>
#include <cstdint>

// Problem constants
#define N_SEL 256
#define PTS   2048
#define D_IN  256
#define D_OUT 256
#define TILES 8

// Tiling
#define TILE_M 128
#define TILE_N 128
#define KC     32
#define NTHREADS 256
#define NCHUNK (D_IN / KC)      // 8

// Smem layout: k-pair interleaved, row stride 40 floats (stride8 = 20 == 4 mod 16
// -> conflict-free LDS.64 fragment loads). A rows 0..127, B rows (n) 0..127.
#define STRIDE   40
#define B_OFF_F  (128 * STRIDE)          // 5120 floats
#define STAGE_F  (256 * STRIDE)          // 10240 floats
#define SMEM_DYN (2 * STAGE_F * 4)       // 81920 bytes (double buffered)

__device__ int g_t;
__device__ int g_idx[N_SEL];

// Resolve t and indices (handles both int32 and int64 index dtype).
__global__ void setup_kernel(const int* __restrict__ idx_words,
                             const int* __restrict__ t_words, int has_t) {
    __shared__ int is64;
    if (threadIdx.x == 0) {
        g_t = has_t ? t_words[0] : 3;
        int oro = 0;
        for (int i = 1; i < 256; i += 2) oro |= idx_words[i];
        is64 = (oro == 0) ? 1 : 0;
    }
    __syncthreads();
    int i = threadIdx.x;
    if (i < N_SEL) g_idx[i] = is64 ? idx_words[2 * i] : idx_words[i];
}

__device__ __forceinline__ uint32_t f2tf32(float x) {
    uint32_t u;
    asm("cvt.rna.tf32.f32 %0, %1;" : "=r"(u) : "f"(x));
    return u;
}

// 4-way select (k is runtime; compiles to SEL chain, no local memory)
__device__ __forceinline__ float pick(float4 v, int k) {
    float r = v.x;
    if (k == 1) r = v.y;
    if (k == 2) r = v.z;
    if (k == 3) r = v.w;
    return r;
}

__global__ void __launch_bounds__(NTHREADS, 2)
gemm_tf32_kernel(const float* __restrict__ X, const float* __restrict__ W,
                 const float* __restrict__ Bs, float* __restrict__ O)
{
    extern __shared__ float sm[];
    const int tid  = threadIdx.x;
    const int lane = tid & 31;
    const int warp = tid >> 5;
    const int warp_m = warp & 1;       // 2 x 64-row warp tiles
    const int warp_n = warp >> 1;      // 4 x 32-col warp tiles

    const int bidx  = blockIdx.x;
    const int batch = bidx >> 5;
    const int tile  = bidx & 31;
    const int m0 = (tile >> 1) * TILE_M;
    const int n0 = (tile & 1) * TILE_N;

    const int ch = g_idx[batch];
    const int t  = g_t;
    const float* Ag = X + ((size_t)batch * PTS + m0) * D_IN;
    const float* Wg = W + ((size_t)ch * TILES + t) * (size_t)(D_IN * D_OUT) + n0;
    const float* Bg = Bs + ((size_t)ch * TILES + t) * D_OUT + n0;

    // ---- staging thread geometry ----
    // A: thread -> (row ra (+64), k-group ga). 32B contiguous LDG per row segment.
    const int ga   = lane & 3;
    const int rsub = lane >> 2;              // 0..7
    const int ra   = warp * 8 + rsub;        // 0..63 ; +64 for i=1
    // B: thread -> (k-pair kkb in group gb, n-block nb of 8). Loads rows k,k+4.
    const int kkb = lane & 3;
    const int gb  = (lane >> 2) & 3;
    const int nh  = lane >> 4;
    const int nb  = warp * 16 + nh * 8;

    const float* aptr = Ag + (size_t)ra * D_IN + ga * 8;
    const float* bptr = Wg + (size_t)(gb * 8 + kkb) * D_OUT + nb;

    // ---- consumer fragment bases (float units) ----
    const int a_base = (warp_m * 64 + (lane >> 2)) * STRIDE + (lane & 3) * 2;
    const int b_base = B_OFF_F + (warp_n * 32 + (lane >> 2)) * STRIDE + (lane & 3) * 2;

    float acc[4][4][4];
#pragma unroll
    for (int mi = 0; mi < 4; mi++)
#pragma unroll
        for (int ni = 0; ni < 4; ni++)
#pragma unroll
            for (int r = 0; r < 4; r++) acc[mi][ni][r] = 0.0f;

    float4 aR[2][2], bR[4];

    auto loadg = [&](int c) {
        const float* ap = aptr + c * KC;
        aR[0][0] = *(const float4*)(ap);
        aR[0][1] = *(const float4*)(ap + 4);
        aR[1][0] = *(const float4*)(ap + 64 * D_IN);
        aR[1][1] = *(const float4*)(ap + 64 * D_IN + 4);
        const float* bp = bptr + (size_t)c * KC * D_OUT;
        bR[0] = *(const float4*)(bp);                // (k,   nb..nb+3)
        bR[1] = *(const float4*)(bp + 4);            // (k,   nb+4..nb+7)
        bR[2] = *(const float4*)(bp + 4 * D_OUT);    // (k+4, nb..nb+3)
        bR[3] = *(const float4*)(bp + 4 * D_OUT + 4);
    };

    auto storesm = [&](int s) {
        float* base = sm + s * STAGE_F;
        // A: pairs (k, k+4) -> contiguous 8B; write order rotated by rsub
        // so each STS.64 instruction hits 16 distinct bank-pairs.
#pragma unroll
        for (int i = 0; i < 2; i++) {
            float* arow = base + (ra + i * 64) * STRIDE + ga * 8;
#pragma unroll
            for (int j = 0; j < 4; j++) {
                int kk = (j + rsub) & 3;
                uint2 v;
                v.x = f2tf32(pick(aR[i][0], kk));
                v.y = f2tf32(pick(aR[i][1], kk));
                *(uint2*)(arow + kk * 2) = v;
            }
        }
        // B: transpose to [n][k-pair]; lanes span (gb,kkb) -> conflict-free.
        float* brow = base + B_OFF_F + nb * STRIDE + gb * 8 + kkb * 2;
#pragma unroll
        for (int j = 0; j < 8; j++) {
            float lo = (j < 4) ? ((const float*)&bR[0])[j] : ((const float*)&bR[1])[j - 4];
            float hi = (j < 4) ? ((const float*)&bR[2])[j] : ((const float*)&bR[3])[j - 4];
            uint2 v;
            v.x = f2tf32(lo);
            v.y = f2tf32(hi);
            *(uint2*)(brow + j * STRIDE) = v;
        }
    };

    auto consume = [&](int s) {
        const float* buf = sm + s * STAGE_F;
#pragma unroll
        for (int g = 0; g < 4; g++) {
            uint2 a[4][2], b[4];
#pragma unroll
            for (int mi = 0; mi < 4; mi++) {
                a[mi][0] = *(const uint2*)(buf + a_base + (mi * 16) * STRIDE + g * 8);
                a[mi][1] = *(const uint2*)(buf + a_base + (mi * 16 + 8) * STRIDE + g * 8);
            }
#pragma unroll
            for (int ni = 0; ni < 4; ni++)
                b[ni] = *(const uint2*)(buf + b_base + (ni * 8) * STRIDE + g * 8);
#pragma unroll
            for (int mi = 0; mi < 4; mi++)
#pragma unroll
                for (int ni = 0; ni < 4; ni++) {
                    asm volatile(
                        "mma.sync.aligned.m16n8k8.row.col.f32.tf32.tf32.f32 "
                        "{%0,%1,%2,%3}, {%4,%5,%6,%7}, {%8,%9}, {%0,%1,%2,%3};\n"
                        : "+f"(acc[mi][ni][0]), "+f"(acc[mi][ni][1]),
                          "+f"(acc[mi][ni][2]), "+f"(acc[mi][ni][3])
                        : "r"(a[mi][0].x), "r"(a[mi][1].x),
                          "r"(a[mi][0].y), "r"(a[mi][1].y),
                          "r"(b[ni].x), "r"(b[ni].y));
                }
        }
    };

    loadg(0);
    storesm(0);
    __syncthreads();

#pragma unroll 2
    for (int c = 0; c < NCHUNK; c++) {
        if (c + 1 < NCHUNK) loadg(c + 1);
        consume(c & 1);
        if (c + 1 < NCHUNK) {
            storesm((c + 1) & 1);
            __syncthreads();
        }
    }

    // ---- epilogue: + bias, write fp32 ----
    float2 bv[4];
#pragma unroll
    for (int ni = 0; ni < 4; ni++) {
        const int col = warp_n * 32 + ni * 8 + (lane & 3) * 2;
        bv[ni] = *(const float2*)(Bg + col);
    }
#pragma unroll
    for (int mi = 0; mi < 4; mi++) {
        const int r0 = m0 + warp_m * 64 + mi * 16 + (lane >> 2);
        float* o0 = O + ((size_t)batch * PTS + r0) * D_OUT + n0;
        float* o1 = o0 + (size_t)8 * D_OUT;
#pragma unroll
        for (int ni = 0; ni < 4; ni++) {
            const int col = warp_n * 32 + ni * 8 + (lane & 3) * 2;
            float2 v0 = { acc[mi][ni][0] + bv[ni].x, acc[mi][ni][1] + bv[ni].y };
            float2 v1 = { acc[mi][ni][2] + bv[ni].x, acc[mi][ni][3] + bv[ni].y };
            *(float2*)(o0 + col) = v0;
            *(float2*)(o1 + col) = v1;
        }
    }
}

extern "C" void kernel_launch(void* const* d_in, const int* in_sizes, int n_in,
                              void* d_out, int out_size) {
    const float* x   = (const float*)d_in[0];
    const float* w   = (const float*)d_in[1];
    const float* b   = (const float*)d_in[2];
    const int*   idx = (const int*)d_in[3];
    const int*   tp  = (n_in > 4) ? (const int*)d_in[4] : nullptr;
    float*       out = (float*)d_out;

    (void)in_sizes; (void)out_size;

    cudaFuncSetAttribute(gemm_tf32_kernel,
                         cudaFuncAttributeMaxDynamicSharedMemorySize, SMEM_DYN);

    setup_kernel<<<1, 256>>>(idx, tp, (n_in > 4) ? 1 : 0);

    const int grid = N_SEL * (PTS / TILE_M) * (D_OUT / TILE_N);  // 8192
    gemm_tf32_kernel<<<grid, NTHREADS, SMEM_DYN>>>(x, w, b, out);
}